// round 5
// baseline (speedup 1.0000x reference)
#include <cuda_runtime.h>
#include <cstdint>

#define B_ 4
#define L_ 2048
#define D_ 1024
#define H_ 16
#define HD_ 64
#define M_ 8192

// ---------------- scratch ----------------
__device__ float g_h[M_ * D_];       // pre-LN output (tf32-rounded), residual source
__device__ float g_q[M_ * D_];       // [B*H][L][HD], tf32
__device__ float g_k[M_ * D_];
__device__ float g_v[M_ * D_];
__device__ float g_att[M_ * D_];     // attention out (B,L,D), tf32
__device__ float g_y[M_ * D_];       // o-proj + residual (fp32)
__device__ float g_wqkv[3 * D_ * D_]; // tf32 weights, concatenated [Wq;Wk;Wv]
__device__ float g_wo4[D_ * D_];
__device__ int   g_len[B_];

// ---------------- helpers ----------------
__device__ __forceinline__ float tf32r(float x) {
    float y; asm("cvt.rna.tf32.f32 %0, %1;" : "=f"(y) : "f"(x)); return y;
}
#define CPA16(dst, src) asm volatile("cp.async.cg.shared.global [%0], [%1], 16;\n" ::"r"(dst), "l"(src))
#define CPA_COMMIT asm volatile("cp.async.commit_group;\n")

__device__ __forceinline__ void mma_tf32(float& c0, float& c1, float& c2, float& c3,
                                         uint32_t a0, uint32_t a1, uint32_t a2, uint32_t a3,
                                         uint32_t b0, uint32_t b1) {
    asm volatile(
        "mma.sync.aligned.m16n8k8.row.col.f32.tf32.tf32.f32 "
        "{%0,%1,%2,%3}, {%4,%5,%6,%7}, {%8,%9}, {%0,%1,%2,%3};\n"
        : "+f"(c0), "+f"(c1), "+f"(c2), "+f"(c3)
        : "r"(a0), "r"(a1), "r"(a2), "r"(a3), "r"(b0), "r"(b1));
}

// ---------------- mask -> lengths (monotone per spec) ----------------
__global__ void mask_len_kernel(const unsigned int* __restrict__ pw) {
    __shared__ int s_bad;
    int t = threadIdx.x;
    if (t == 0) s_bad = 0;
    if (t < B_) g_len[t] = L_;
    __syncthreads();
    int bad = 0;
    for (int i = t; i < (B_ * L_) / 4; i += 256) {
        unsigned v = pw[i];
        if (v != 0u && v != 1u && v != 0x3F800000u) bad = 1;
    }
    if (bad) atomicExch(&s_bad, 1);
    __syncthreads();
    if (s_bad) {
        const unsigned char* pb = (const unsigned char*)pw;
        for (int i = t; i < B_ * L_; i += 256)
            if (pb[i]) atomicMin(&g_len[i >> 11], i & (L_ - 1));
    } else {
        for (int i = t; i < B_ * L_; i += 256)
            if (pw[i]) atomicMin(&g_len[i >> 11], i & (L_ - 1));
    }
}

// ---------------- weight tf32 pre-round ----------------
__global__ void wround_kernel(const float* __restrict__ a, const float* __restrict__ b,
                              const float* __restrict__ c, const float* __restrict__ d) {
    int i = blockIdx.x * 256 + threadIdx.x;
    g_wqkv[i]               = tf32r(a[i]);
    g_wqkv[D_ * D_ + i]     = tf32r(b[i]);
    g_wqkv[2 * D_ * D_ + i] = tf32r(c[i]);
    g_wo4[i]                = tf32r(d[i]);
}

// ---------------- LayerNorm ----------------
__global__ void ln_kernel(const float* __restrict__ x, const float* __restrict__ gamma,
                          const float* __restrict__ beta, float* __restrict__ out, int rnd) {
    __shared__ float red[8];
    __shared__ float s_mu, s_rs;
    int row = blockIdx.x;
    int t = threadIdx.x;
    float4 v = ((const float4*)(x + (size_t)row * D_))[t];
    float s = v.x + v.y + v.z + v.w;
    #pragma unroll
    for (int o = 16; o; o >>= 1) s += __shfl_xor_sync(0xffffffffu, s, o);
    if ((t & 31) == 0) red[t >> 5] = s;
    __syncthreads();
    if (t == 0) {
        float tot = 0.f;
        #pragma unroll
        for (int i = 0; i < 8; i++) tot += red[i];
        s_mu = tot * (1.0f / D_);
    }
    __syncthreads();
    float mu = s_mu;
    float dx = v.x - mu, dy = v.y - mu, dz = v.z - mu, dw = v.w - mu;
    float ss = dx * dx + dy * dy + dz * dz + dw * dw;
    #pragma unroll
    for (int o = 16; o; o >>= 1) ss += __shfl_xor_sync(0xffffffffu, ss, o);
    __syncthreads();
    if ((t & 31) == 0) red[t >> 5] = ss;
    __syncthreads();
    if (t == 0) {
        float tot = 0.f;
        #pragma unroll
        for (int i = 0; i < 8; i++) tot += red[i];
        s_rs = rsqrtf(tot * (1.0f / D_) + 1e-5f);
    }
    __syncthreads();
    float rs = s_rs;
    float4 gv = ((const float4*)gamma)[t];
    float4 bv = ((const float4*)beta)[t];
    float4 o4;
    o4.x = dx * rs * gv.x + bv.x;
    o4.y = dy * rs * gv.y + bv.y;
    o4.z = dz * rs * gv.z + bv.z;
    o4.w = dw * rs * gv.w + bv.w;
    if (rnd) { o4.x = tf32r(o4.x); o4.y = tf32r(o4.y); o4.z = tf32r(o4.z); o4.w = tf32r(o4.w); }
    ((float4*)(out + (size_t)row * D_))[t] = o4;
}

// ---------------- tf32 TC GEMM: C = A(MxK) x W(NxK)^T + bias ----------------
// Block 128(m) x 256(n), BK=32, 3-stage cp.async, 1 sync/iter, frag double-buffer.
// mode 1: QKV fused (N=3072), scatter to [B*H][L][HD] + tf32 round.
// mode 0: row-major + residual.
#define BK_ 32
#define AST 36
#define NK_ (D_ / BK_)
__global__ __launch_bounds__(256, 1) void tgemm_kernel(
    const float* __restrict__ A, const float* __restrict__ W,
    const float* __restrict__ bias0, const float* __restrict__ bias1,
    const float* __restrict__ bias2, const float* __restrict__ res,
    float* __restrict__ C0, float* __restrict__ C1, float* __restrict__ C2,
    int mode) {
    extern __shared__ float sm[];
    float* As = sm;                     // [3][128][36]
    float* Bs = sm + 3 * 128 * AST;     // [3][256][36]
    int t = threadIdx.x, w = t >> 5, lane = t & 31;
    int r = lane >> 2, c4 = lane & 3;
    int m0 = blockIdx.y * 128, n0 = blockIdx.x * 256;
    int wm = w >> 2, wn = w & 3;

    float acc[4][8][4] = {};

    auto load_stage = [&](int st, int k0) {
        uint32_t sa = (uint32_t)__cvta_generic_to_shared(As + st * 128 * AST);
        uint32_t sb = (uint32_t)__cvta_generic_to_shared(Bs + st * 256 * AST);
        #pragma unroll
        for (int i = 0; i < 12; i++) {
            int cid = t + i * 256;
            if (cid < 1024) {
                int row = cid >> 3, kc = (cid & 7) * 4;
                CPA16(sa + (row * AST + kc) * 4, A + (size_t)(m0 + row) * D_ + k0 + kc);
            } else {
                int c2 = cid - 1024;
                int row = c2 >> 3, kc = (c2 & 7) * 4;
                CPA16(sb + (row * AST + kc) * 4, W + (size_t)(n0 + row) * D_ + k0 + kc);
            }
        }
    };

    load_stage(0, 0);
    CPA_COMMIT;
    load_stage(1, BK_);
    CPA_COMMIT;

    #pragma unroll 1
    for (int kb = 0; kb < NK_; kb++) {
        if (kb + 1 < NK_) asm volatile("cp.async.wait_group 1;\n");
        else              asm volatile("cp.async.wait_group 0;\n");
        __syncthreads();
        if (kb + 2 < NK_) {
            load_stage((kb + 2) % 3, (kb + 2) * BK_);
            CPA_COMMIT;
        }
        const float* as = As + (kb % 3) * 128 * AST + (wm * 64) * AST;
        const float* bs = Bs + (kb % 3) * 256 * AST + (wn * 64) * AST;

        uint32_t afA[4][4], bfA[8][2], afB[4][4], bfB[8][2];
        #pragma unroll
        for (int mt = 0; mt < 4; mt++) {
            const float* p = as + (mt * 16 + r) * AST + c4;
            afA[mt][0] = __float_as_uint(p[0]);
            afA[mt][1] = __float_as_uint(p[8 * AST]);
            afA[mt][2] = __float_as_uint(p[4]);
            afA[mt][3] = __float_as_uint(p[8 * AST + 4]);
        }
        #pragma unroll
        for (int nt = 0; nt < 8; nt++) {
            const float* p = bs + (nt * 8 + r) * AST + c4;
            bfA[nt][0] = __float_as_uint(p[0]);
            bfA[nt][1] = __float_as_uint(p[4]);
        }
        #pragma unroll
        for (int ks = 0; ks < 4; ks++) {
            // prefetch next kstep fragments into the alternate set
            if (ks < 3) {
                int kk = (ks + 1) * 8;
                uint32_t (*afN)[4] = (ks & 1) ? afA : afB;
                uint32_t (*bfN)[2] = (ks & 1) ? bfA : bfB;
                #pragma unroll
                for (int mt = 0; mt < 4; mt++) {
                    const float* p = as + (mt * 16 + r) * AST + kk + c4;
                    afN[mt][0] = __float_as_uint(p[0]);
                    afN[mt][1] = __float_as_uint(p[8 * AST]);
                    afN[mt][2] = __float_as_uint(p[4]);
                    afN[mt][3] = __float_as_uint(p[8 * AST + 4]);
                }
                #pragma unroll
                for (int nt = 0; nt < 8; nt++) {
                    const float* p = bs + (nt * 8 + r) * AST + kk + c4;
                    bfN[nt][0] = __float_as_uint(p[0]);
                    bfN[nt][1] = __float_as_uint(p[4]);
                }
            }
            uint32_t (*af)[4] = (ks & 1) ? afB : afA;
            uint32_t (*bf)[2] = (ks & 1) ? bfB : bfA;
            #pragma unroll
            for (int mt = 0; mt < 4; mt++)
                #pragma unroll
                for (int nt = 0; nt < 8; nt++)
                    mma_tf32(acc[mt][nt][0], acc[mt][nt][1], acc[mt][nt][2], acc[mt][nt][3],
                             af[mt][0], af[mt][1], af[mt][2], af[mt][3],
                             bf[nt][0], bf[nt][1]);
        }
        __syncthreads();
    }

    int mrow = m0 + wm * 64, ncol = n0 + wn * 64;
    if (mode == 1) {
        int mat = ncol >> 10;
        int dbase = ncol & 1023;
        const float* bias = (mat == 0) ? bias0 : (mat == 1) ? bias1 : bias2;
        float* C = (mat == 0) ? C0 : (mat == 1) ? C1 : C2;
        #pragma unroll
        for (int mt = 0; mt < 4; mt++) {
            int row0 = mrow + mt * 16 + r;
            int bidx = row0 >> 11, l = row0 & (L_ - 1);
            #pragma unroll
            for (int nt = 0; nt < 8; nt++) {
                int dcol = dbase + nt * 8 + 2 * c4;
                int head = dcol >> 6, hd = dcol & 63;
                float b0 = bias[dcol], b1 = bias[dcol + 1];
                float* d0 = C + ((size_t)(bidx * H_ + head) * L_ + l) * HD_ + hd;
                float* d1 = C + ((size_t)(bidx * H_ + head) * L_ + l + 8) * HD_ + hd;
                float2 v0 = {tf32r(acc[mt][nt][0] + b0), tf32r(acc[mt][nt][1] + b1)};
                float2 v1 = {tf32r(acc[mt][nt][2] + b0), tf32r(acc[mt][nt][3] + b1)};
                *(float2*)d0 = v0;
                *(float2*)d1 = v1;
            }
        }
    } else {
        #pragma unroll
        for (int mt = 0; mt < 4; mt++) {
            int row0 = mrow + mt * 16 + r;
            #pragma unroll
            for (int nt = 0; nt < 8; nt++) {
                int col = ncol + nt * 8 + 2 * c4;
                float b0 = bias0[col], b1 = bias0[col + 1];
                float2 r0 = *(const float2*)(res + (size_t)row0 * D_ + col);
                float2 r1 = *(const float2*)(res + (size_t)(row0 + 8) * D_ + col);
                float2 v0 = {acc[mt][nt][0] + b0 + r0.x, acc[mt][nt][1] + b1 + r0.y};
                float2 v1 = {acc[mt][nt][2] + b0 + r1.x, acc[mt][nt][3] + b1 + r1.y};
                *(float2*)(C0 + (size_t)row0 * D_ + col) = v0;
                *(float2*)(C0 + (size_t)(row0 + 8) * D_ + col) = v1;
            }
        }
    }
}

// ---------------- tf32 TC flash attention ----------------
// CTA: 256 query rows, 8 warps x 32 rows (two 16-row m-tiles). K-tile 64,
// cp.async double-buffered. Q staged in smem (loaded once).
#define QSTR 68
#define KSTR 68
#define VSTR 72
#define PSTR 68
__global__ __launch_bounds__(256, 1) void attn_tc_kernel(
    const float* __restrict__ Q, const float* __restrict__ K,
    const float* __restrict__ V, float* __restrict__ O) {
    extern __shared__ float sm[];
    float* Qs = sm;                       // [256][68]
    float* Ks = Qs + 256 * QSTR;          // [2][64][68]
    float* Vs = Ks + 2 * 64 * KSTR;       // [2][64][72]
    float* Ps = Vs + 2 * 64 * VSTR;       // [8][32][68]
    int t = threadIdx.x, w = t >> 5, lane = t & 31;
    int r = lane >> 2, c4 = lane & 3;
    int qt = gridDim.x - 1 - blockIdx.x;  // longest first
    int bh = blockIdx.y;
    int bidx = bh >> 4, head = bh & (H_ - 1);
    int len = g_len[bidx];
    int qbase = qt * 256;
    int gqw = qbase + w * 32;

    // stage Q (256x64), scale by 1/sqrt(64)=0.125 (exact power of two)
    const float* Qb = Q + ((size_t)bh * L_ + qbase) * HD_;
    #pragma unroll
    for (int i = 0; i < 16; i++) {
        int cid = t + i * 256;
        int row = cid >> 4, kc = (cid & 15) * 4;
        float4 v4 = *(const float4*)(Qb + row * 64 + kc);
        v4.x *= 0.125f; v4.y *= 0.125f; v4.z *= 0.125f; v4.w *= 0.125f;
        *(float4*)(Qs + row * QSTR + kc) = v4;
    }

    float o_[2][8][4] = {};
    float mv[2][2] = {{-1e30f, -1e30f}, {-1e30f, -1e30f}};
    float lv[2][2] = {{0.f, 0.f}, {0.f, 0.f}};
    float* pw = Ps + w * 32 * PSTR;
    int nkt = qt * 4 + 4;

    auto load_stage = [&](int st, int kt2) {
        const float* Kb = K + ((size_t)bh * L_ + kt2 * 64) * HD_;
        const float* Vb = V + ((size_t)bh * L_ + kt2 * 64) * HD_;
        uint32_t sk = (uint32_t)__cvta_generic_to_shared(Ks + st * 64 * KSTR);
        uint32_t sv = (uint32_t)__cvta_generic_to_shared(Vs + st * 64 * VSTR);
        #pragma unroll
        for (int i = 0; i < 4; i++) {
            int cid = t + i * 256;
            int row = cid >> 4, kc = (cid & 15) * 4;
            CPA16(sk + (row * KSTR + kc) * 4, Kb + row * 64 + kc);
        }
        #pragma unroll
        for (int i = 0; i < 4; i++) {
            int cid = t + i * 256;
            int row = cid >> 4, kc = (cid & 15) * 4;
            CPA16(sv + (row * VSTR + kc) * 4, Vb + row * 64 + kc);
        }
    };

    load_stage(0, 0);
    CPA_COMMIT;
    #pragma unroll 1
    for (int kt = 0; kt < nkt; kt++) {
        if (kt + 1 < nkt) {
            load_stage((kt + 1) & 1, kt + 1);
            CPA_COMMIT;
            asm volatile("cp.async.wait_group 1;\n");
        } else {
            asm volatile("cp.async.wait_group 0;\n");
        }
        __syncthreads();
        int kbase = kt * 64;
        if (kbase <= gqw + 31 && kbase < len) {
            const float* ks_ = Ks + (kt & 1) * 64 * KSTR;
            const float* vs_ = Vs + (kt & 1) * 64 * VSTR;
            // ---- S = Q K^T : two 16x64 m-tiles per warp ----
            float s[2][8][4] = {};
            #pragma unroll
            for (int ks = 0; ks < 8; ks++) {
                uint32_t bf[8][2];
                #pragma unroll
                for (int nt = 0; nt < 8; nt++) {
                    const float* p = ks_ + (nt * 8 + r) * KSTR + ks * 8 + c4;
                    bf[nt][0] = __float_as_uint(p[0]);
                    bf[nt][1] = __float_as_uint(p[4]);
                }
                uint32_t af[2][4];
                #pragma unroll
                for (int mt = 0; mt < 2; mt++) {
                    const float* p = Qs + (w * 32 + mt * 16 + r) * QSTR + ks * 8 + c4;
                    af[mt][0] = __float_as_uint(p[0]);
                    af[mt][1] = __float_as_uint(p[8 * QSTR]);
                    af[mt][2] = __float_as_uint(p[4]);
                    af[mt][3] = __float_as_uint(p[8 * QSTR + 4]);
                }
                #pragma unroll
                for (int mt = 0; mt < 2; mt++)
                    #pragma unroll
                    for (int nt = 0; nt < 8; nt++)
                        mma_tf32(s[mt][nt][0], s[mt][nt][1], s[mt][nt][2], s[mt][nt][3],
                                 af[mt][0], af[mt][1], af[mt][2], af[mt][3],
                                 bf[nt][0], bf[nt][1]);
            }
            // ---- mask + online softmax + P store (per m-tile) ----
            #pragma unroll
            for (int mt = 0; mt < 2; mt++) {
                int gq0 = gqw + mt * 16 + r, gq1 = gq0 + 8;
                bool full = (kbase + 63 <= gqw + mt * 16) && (kbase + 64 <= len);
                if (!full) {
                    #pragma unroll
                    for (int nt = 0; nt < 8; nt++) {
                        int kc = kbase + nt * 8 + 2 * c4;
                        if (!(kc     <= gq0 && kc     < len)) s[mt][nt][0] = -1e30f;
                        if (!(kc + 1 <= gq0 && kc + 1 < len)) s[mt][nt][1] = -1e30f;
                        if (!(kc     <= gq1 && kc     < len)) s[mt][nt][2] = -1e30f;
                        if (!(kc + 1 <= gq1 && kc + 1 < len)) s[mt][nt][3] = -1e30f;
                    }
                }
                float mx0 = -1e30f, mx1 = -1e30f;
                #pragma unroll
                for (int nt = 0; nt < 8; nt++) {
                    mx0 = fmaxf(mx0, fmaxf(s[mt][nt][0], s[mt][nt][1]));
                    mx1 = fmaxf(mx1, fmaxf(s[mt][nt][2], s[mt][nt][3]));
                }
                mx0 = fmaxf(mx0, __shfl_xor_sync(0xffffffffu, mx0, 1));
                mx0 = fmaxf(mx0, __shfl_xor_sync(0xffffffffu, mx0, 2));
                mx1 = fmaxf(mx1, __shfl_xor_sync(0xffffffffu, mx1, 1));
                mx1 = fmaxf(mx1, __shfl_xor_sync(0xffffffffu, mx1, 2));
                float nm0 = fmaxf(mv[mt][0], mx0), nm1 = fmaxf(mv[mt][1], mx1);
                float sc0 = __expf(mv[mt][0] - nm0), sc1 = __expf(mv[mt][1] - nm1);
                mv[mt][0] = nm0; mv[mt][1] = nm1;
                float rs0 = 0.f, rs1 = 0.f;
                #pragma unroll
                for (int nt = 0; nt < 8; nt++) {
                    s[mt][nt][0] = __expf(s[mt][nt][0] - nm0); rs0 += s[mt][nt][0];
                    s[mt][nt][1] = __expf(s[mt][nt][1] - nm0); rs0 += s[mt][nt][1];
                    s[mt][nt][2] = __expf(s[mt][nt][2] - nm1); rs1 += s[mt][nt][2];
                    s[mt][nt][3] = __expf(s[mt][nt][3] - nm1); rs1 += s[mt][nt][3];
                }
                rs0 += __shfl_xor_sync(0xffffffffu, rs0, 1);
                rs0 += __shfl_xor_sync(0xffffffffu, rs0, 2);
                rs1 += __shfl_xor_sync(0xffffffffu, rs1, 1);
                rs1 += __shfl_xor_sync(0xffffffffu, rs1, 2);
                lv[mt][0] = lv[mt][0] * sc0 + rs0;
                lv[mt][1] = lv[mt][1] * sc1 + rs1;
                #pragma unroll
                for (int nt = 0; nt < 8; nt++) {
                    o_[mt][nt][0] *= sc0; o_[mt][nt][1] *= sc0;
                    o_[mt][nt][2] *= sc1; o_[mt][nt][3] *= sc1;
                    float2 p0 = {tf32r(s[mt][nt][0]), tf32r(s[mt][nt][1])};
                    float2 p1 = {tf32r(s[mt][nt][2]), tf32r(s[mt][nt][3])};
                    *(float2*)(pw + (mt * 16 + r) * PSTR + nt * 8 + 2 * c4) = p0;
                    *(float2*)(pw + (mt * 16 + r + 8) * PSTR + nt * 8 + 2 * c4) = p1;
                }
            }
            __syncwarp();
            // ---- O += P V ----
            #pragma unroll
            for (int ks = 0; ks < 8; ks++) {
                uint32_t af[2][4];
                #pragma unroll
                for (int mt = 0; mt < 2; mt++) {
                    const float* p = pw + (mt * 16 + r) * PSTR + ks * 8 + c4;
                    af[mt][0] = __float_as_uint(p[0]);
                    af[mt][1] = __float_as_uint(p[8 * PSTR]);
                    af[mt][2] = __float_as_uint(p[4]);
                    af[mt][3] = __float_as_uint(p[8 * PSTR + 4]);
                }
                #pragma unroll
                for (int nt = 0; nt < 8; nt++) {
                    uint32_t b0 = __float_as_uint(vs_[(ks * 8 + c4) * VSTR + nt * 8 + r]);
                    uint32_t b1 = __float_as_uint(vs_[(ks * 8 + c4 + 4) * VSTR + nt * 8 + r]);
                    #pragma unroll
                    for (int mt = 0; mt < 2; mt++)
                        mma_tf32(o_[mt][nt][0], o_[mt][nt][1], o_[mt][nt][2], o_[mt][nt][3],
                                 af[mt][0], af[mt][1], af[mt][2], af[mt][3],
                                 b0, b1);
                }
            }
            __syncwarp();
        }
        __syncthreads();
    }

    size_t ob = (size_t)bidx * L_ + gqw;
    #pragma unroll
    for (int mt = 0; mt < 2; mt++) {
        float inv0 = 1.0f / lv[mt][0], inv1 = 1.0f / lv[mt][1];
        #pragma unroll
        for (int nt = 0; nt < 8; nt++) {
            int col = head * HD_ + nt * 8 + 2 * c4;
            float2 v0 = {tf32r(o_[mt][nt][0] * inv0), tf32r(o_[mt][nt][1] * inv0)};
            float2 v1 = {tf32r(o_[mt][nt][2] * inv1), tf32r(o_[mt][nt][3] * inv1)};
            *(float2*)(O + (ob + mt * 16 + r) * D_ + col) = v0;
            *(float2*)(O + (ob + mt * 16 + r + 8) * D_ + col) = v1;
        }
    }
}

// ---------------- launch ----------------
extern "C" void kernel_launch(void* const* d_in, const int* in_sizes, int n_in,
                              void* d_out, int out_size) {
    const float* x     = (const float*)d_in[0];
    const void*  pmask = d_in[1];
    const float* Wq = (const float*)d_in[3];
    const float* bq = (const float*)d_in[4];
    const float* Wk = (const float*)d_in[5];
    const float* bk = (const float*)d_in[6];
    const float* Wv = (const float*)d_in[7];
    const float* bv = (const float*)d_in[8];
    const float* Wo = (const float*)d_in[9];
    const float* bo = (const float*)d_in[10];
    const float* g_pre = (const float*)d_in[11];
    const float* b_pre = (const float*)d_in[12];
    const float* g_ln  = (const float*)d_in[13];
    const float* b_ln  = (const float*)d_in[14];
    float* out = (float*)d_out;

    float *h, *q, *k, *v, *att, *y, *wqkv, *wo4;
    cudaGetSymbolAddress((void**)&h,    g_h);
    cudaGetSymbolAddress((void**)&q,    g_q);
    cudaGetSymbolAddress((void**)&k,    g_k);
    cudaGetSymbolAddress((void**)&v,    g_v);
    cudaGetSymbolAddress((void**)&att,  g_att);
    cudaGetSymbolAddress((void**)&y,    g_y);
    cudaGetSymbolAddress((void**)&wqkv, g_wqkv);
    cudaGetSymbolAddress((void**)&wo4,  g_wo4);

    const int gemm_smem = 3 * (128 + 256) * AST * (int)sizeof(float);  // 165888
    const int attn_smem = (256 * QSTR + 2 * 64 * KSTR + 2 * 64 * VSTR + 8 * 32 * PSTR) * (int)sizeof(float); // 210944
    cudaFuncSetAttribute(tgemm_kernel,   cudaFuncAttributeMaxDynamicSharedMemorySize, gemm_smem);
    cudaFuncSetAttribute(attn_tc_kernel, cudaFuncAttributeMaxDynamicSharedMemorySize, attn_smem);

    mask_len_kernel<<<1, 256>>>((const unsigned int*)pmask);
    wround_kernel<<<(D_ * D_) / 256, 256>>>(Wq, Wk, Wv, Wo);
    ln_kernel<<<M_, 256>>>(x, g_pre, b_pre, h, 1);

    // fused QKV projection: N = 3072
    tgemm_kernel<<<dim3(3 * D_ / 256, M_ / 128), 256, gemm_smem>>>(
        h, wqkv, bq, bk, bv, nullptr, q, k, v, 1);

    attn_tc_kernel<<<dim3(L_ / 256, B_ * H_), 256, attn_smem>>>(q, k, v, att);

    // output projection + residual
    tgemm_kernel<<<dim3(D_ / 256, M_ / 128), 256, gemm_smem>>>(
        att, wo4, bo, bo, bo, h, y, y, y, 0);

    ln_kernel<<<M_, 256>>>(y, g_ln, b_ln, out, 0);
}

// round 8
// speedup vs baseline: 1.0277x; 1.0277x over previous
#include <cuda_runtime.h>
#include <cstdint>

#define B_ 4
#define L_ 2048
#define D_ 1024
#define H_ 16
#define HD_ 64
#define M_ 8192

// ---------------- scratch ----------------
__device__ float g_h[M_ * D_];
__device__ float g_q[M_ * D_];
__device__ float g_k[M_ * D_];
__device__ float g_v[M_ * D_];
__device__ float g_att[M_ * D_];
__device__ float g_y[M_ * D_];
__device__ float g_wqkv[3 * D_ * D_];
__device__ float g_wo4[D_ * D_];
__device__ int   g_len[B_];

// ---------------- helpers ----------------
__device__ __forceinline__ float tf32r(float x) {
    float y; asm("cvt.rna.tf32.f32 %0, %1;" : "=f"(y) : "f"(x)); return y;
}
#define CPA16(dst, src) asm volatile("cp.async.cg.shared.global [%0], [%1], 16;\n" ::"r"(dst), "l"(src))
#define CPA_COMMIT asm volatile("cp.async.commit_group;\n")

__device__ __forceinline__ void mma_tf32(float& c0, float& c1, float& c2, float& c3,
                                         uint32_t a0, uint32_t a1, uint32_t a2, uint32_t a3,
                                         uint32_t b0, uint32_t b1) {
    asm volatile(
        "mma.sync.aligned.m16n8k8.row.col.f32.tf32.tf32.f32 "
        "{%0,%1,%2,%3}, {%4,%5,%6,%7}, {%8,%9}, {%0,%1,%2,%3};\n"
        : "+f"(c0), "+f"(c1), "+f"(c2), "+f"(c3)
        : "r"(a0), "r"(a1), "r"(a2), "r"(a3), "r"(b0), "r"(b1));
}

// ---------------- mask -> lengths ----------------
__global__ void mask_len_kernel(const unsigned int* __restrict__ pw) {
    __shared__ int s_bad;
    int t = threadIdx.x;
    if (t == 0) s_bad = 0;
    if (t < B_) g_len[t] = L_;
    __syncthreads();
    int bad = 0;
    for (int i = t; i < (B_ * L_) / 4; i += 256) {
        unsigned v = pw[i];
        if (v != 0u && v != 1u && v != 0x3F800000u) bad = 1;
    }
    if (bad) atomicExch(&s_bad, 1);
    __syncthreads();
    if (s_bad) {
        const unsigned char* pb = (const unsigned char*)pw;
        for (int i = t; i < B_ * L_; i += 256)
            if (pb[i]) atomicMin(&g_len[i >> 11], i & (L_ - 1));
    } else {
        for (int i = t; i < B_ * L_; i += 256)
            if (pw[i]) atomicMin(&g_len[i >> 11], i & (L_ - 1));
    }
}

// ---------------- weight tf32 pre-round ----------------
__global__ void wround_kernel(const float* __restrict__ a, const float* __restrict__ b,
                              const float* __restrict__ c, const float* __restrict__ d) {
    int i = blockIdx.x * 256 + threadIdx.x;
    g_wqkv[i]               = tf32r(a[i]);
    g_wqkv[D_ * D_ + i]     = tf32r(b[i]);
    g_wqkv[2 * D_ * D_ + i] = tf32r(c[i]);
    g_wo4[i]                = tf32r(d[i]);
}

// ---------------- LayerNorm ----------------
__global__ void ln_kernel(const float* __restrict__ x, const float* __restrict__ gamma,
                          const float* __restrict__ beta, float* __restrict__ out, int rnd) {
    __shared__ float red[8];
    __shared__ float s_mu, s_rs;
    int row = blockIdx.x;
    int t = threadIdx.x;
    float4 v = ((const float4*)(x + (size_t)row * D_))[t];
    float s = v.x + v.y + v.z + v.w;
    #pragma unroll
    for (int o = 16; o; o >>= 1) s += __shfl_xor_sync(0xffffffffu, s, o);
    if ((t & 31) == 0) red[t >> 5] = s;
    __syncthreads();
    if (t == 0) {
        float tot = 0.f;
        #pragma unroll
        for (int i = 0; i < 8; i++) tot += red[i];
        s_mu = tot * (1.0f / D_);
    }
    __syncthreads();
    float mu = s_mu;
    float dx = v.x - mu, dy = v.y - mu, dz = v.z - mu, dw = v.w - mu;
    float ss = dx * dx + dy * dy + dz * dz + dw * dw;
    #pragma unroll
    for (int o = 16; o; o >>= 1) ss += __shfl_xor_sync(0xffffffffu, ss, o);
    __syncthreads();
    if ((t & 31) == 0) red[t >> 5] = ss;
    __syncthreads();
    if (t == 0) {
        float tot = 0.f;
        #pragma unroll
        for (int i = 0; i < 8; i++) tot += red[i];
        s_rs = rsqrtf(tot * (1.0f / D_) + 1e-5f);
    }
    __syncthreads();
    float rs = s_rs;
    float4 gv = ((const float4*)gamma)[t];
    float4 bv = ((const float4*)beta)[t];
    float4 o4;
    o4.x = dx * rs * gv.x + bv.x;
    o4.y = dy * rs * gv.y + bv.y;
    o4.z = dz * rs * gv.z + bv.z;
    o4.w = dw * rs * gv.w + bv.w;
    if (rnd) { o4.x = tf32r(o4.x); o4.y = tf32r(o4.y); o4.z = tf32r(o4.z); o4.w = tf32r(o4.w); }
    ((float4*)(out + (size_t)row * D_))[t] = o4;
}

// ---------------- tf32 TC GEMM: C = A(MxK) x W(NxK)^T + bias ----------------
// Block 128(m) x 128(n), 8 warps of 64x32, BK=32, 3-stage cp.async, 1 sync/iter.
// 2 CTAs/SM. mode 1: QKV fused (N=3072), scatter to heads + tf32 round.
// mode 0: row-major + residual.
#define BK_ 32
#define AST 36
#define NK_ (D_ / BK_)
__global__ __launch_bounds__(256, 2) void tgemm_kernel(
    const float* __restrict__ A, const float* __restrict__ W,
    const float* __restrict__ bias0, const float* __restrict__ bias1,
    const float* __restrict__ bias2, const float* __restrict__ res,
    float* __restrict__ C0, float* __restrict__ C1, float* __restrict__ C2,
    int mode) {
    extern __shared__ float sm[];
    float* As = sm;                     // [3][128][36]
    float* Bs = sm + 3 * 128 * AST;     // [3][128][36]
    int t = threadIdx.x, w = t >> 5, lane = t & 31;
    int r = lane >> 2, c4 = lane & 3;
    int m0 = blockIdx.y * 128, n0 = blockIdx.x * 128;
    int wm = w >> 2, wn = w & 3;        // warp tile: rows wm*64, cols wn*32

    float acc[4][4][4] = {};

    auto load_stage = [&](int st, int k0) {
        uint32_t sa = (uint32_t)__cvta_generic_to_shared(As + st * 128 * AST);
        uint32_t sb = (uint32_t)__cvta_generic_to_shared(Bs + st * 128 * AST);
        #pragma unroll
        for (int i = 0; i < 8; i++) {
            int cid = t + i * 256;
            if (cid < 1024) {
                int row = cid >> 3, kc = (cid & 7) * 4;
                CPA16(sa + (row * AST + kc) * 4, A + (size_t)(m0 + row) * D_ + k0 + kc);
            } else {
                int c2 = cid - 1024;
                int row = c2 >> 3, kc = (c2 & 7) * 4;
                CPA16(sb + (row * AST + kc) * 4, W + (size_t)(n0 + row) * D_ + k0 + kc);
            }
        }
    };

    load_stage(0, 0);
    CPA_COMMIT;
    load_stage(1, BK_);
    CPA_COMMIT;

    #pragma unroll 1
    for (int kb = 0; kb < NK_; kb++) {
        if (kb + 1 < NK_) asm volatile("cp.async.wait_group 1;\n");
        else              asm volatile("cp.async.wait_group 0;\n");
        __syncthreads();
        if (kb + 2 < NK_) {
            load_stage((kb + 2) % 3, (kb + 2) * BK_);
            CPA_COMMIT;
        }
        const float* as = As + (kb % 3) * 128 * AST + (wm * 64) * AST;
        const float* bs = Bs + (kb % 3) * 128 * AST + (wn * 32) * AST;
        #pragma unroll
        for (int ks = 0; ks < 4; ks++) {
            int kk = ks * 8;
            uint32_t af[4][4], bf[4][2];
            #pragma unroll
            for (int mt = 0; mt < 4; mt++) {
                const float* p = as + (mt * 16 + r) * AST + kk + c4;
                af[mt][0] = __float_as_uint(p[0]);
                af[mt][1] = __float_as_uint(p[8 * AST]);
                af[mt][2] = __float_as_uint(p[4]);
                af[mt][3] = __float_as_uint(p[8 * AST + 4]);
            }
            #pragma unroll
            for (int nt = 0; nt < 4; nt++) {
                const float* p = bs + (nt * 8 + r) * AST + kk + c4;
                bf[nt][0] = __float_as_uint(p[0]);
                bf[nt][1] = __float_as_uint(p[4]);
            }
            #pragma unroll
            for (int mt = 0; mt < 4; mt++)
                #pragma unroll
                for (int nt = 0; nt < 4; nt++)
                    mma_tf32(acc[mt][nt][0], acc[mt][nt][1], acc[mt][nt][2], acc[mt][nt][3],
                             af[mt][0], af[mt][1], af[mt][2], af[mt][3],
                             bf[nt][0], bf[nt][1]);
        }
        __syncthreads();
    }

    int mrow = m0 + wm * 64, ncol = n0 + wn * 32;
    if (mode == 1) {
        int mat = ncol >> 10;
        int dbase = ncol & 1023;
        const float* bias = (mat == 0) ? bias0 : (mat == 1) ? bias1 : bias2;
        float* C = (mat == 0) ? C0 : (mat == 1) ? C1 : C2;
        #pragma unroll
        for (int mt = 0; mt < 4; mt++) {
            int row0 = mrow + mt * 16 + r;
            int bidx = row0 >> 11, l = row0 & (L_ - 1);
            #pragma unroll
            for (int nt = 0; nt < 4; nt++) {
                int dcol = dbase + nt * 8 + 2 * c4;
                int head = dcol >> 6, hd = dcol & 63;
                float b0 = bias[dcol], b1 = bias[dcol + 1];
                float* d0 = C + ((size_t)(bidx * H_ + head) * L_ + l) * HD_ + hd;
                float* d1 = C + ((size_t)(bidx * H_ + head) * L_ + l + 8) * HD_ + hd;
                float2 v0 = {tf32r(acc[mt][nt][0] + b0), tf32r(acc[mt][nt][1] + b1)};
                float2 v1 = {tf32r(acc[mt][nt][2] + b0), tf32r(acc[mt][nt][3] + b1)};
                *(float2*)d0 = v0;
                *(float2*)d1 = v1;
            }
        }
    } else {
        #pragma unroll
        for (int mt = 0; mt < 4; mt++) {
            int row0 = mrow + mt * 16 + r;
            #pragma unroll
            for (int nt = 0; nt < 4; nt++) {
                int col = ncol + nt * 8 + 2 * c4;
                float b0 = bias0[col], b1 = bias0[col + 1];
                float2 r0 = *(const float2*)(res + (size_t)row0 * D_ + col);
                float2 r1 = *(const float2*)(res + (size_t)(row0 + 8) * D_ + col);
                float2 v0 = {acc[mt][nt][0] + b0 + r0.x, acc[mt][nt][1] + b1 + r0.y};
                float2 v1 = {acc[mt][nt][2] + b0 + r1.x, acc[mt][nt][3] + b1 + r1.y};
                *(float2*)(C0 + (size_t)row0 * D_ + col) = v0;
                *(float2*)(C0 + (size_t)(row0 + 8) * D_ + col) = v1;
            }
        }
    }
}

// ---------------- tf32 TC flash attention ----------------
// CTA: 64 query rows, 4 warps x 16 rows. K-tile 64, cp.async double-buffered.
// 2 CTAs/SM (smem 89KB, regs free at 256 thr/SM).
#define KSTR 68
#define VSTR 72
#define PSTR 68
__global__ __launch_bounds__(128, 2) void attn_tc_kernel(
    const float* __restrict__ Q, const float* __restrict__ K,
    const float* __restrict__ V, float* __restrict__ O) {
    extern __shared__ float sm[];
    float* Ks = sm;                       // [2][64][68]
    float* Vs = Ks + 2 * 64 * KSTR;       // [2][64][72]
    float* Ps = Vs + 2 * 64 * VSTR;       // [4][16][68]
    int t = threadIdx.x, w = t >> 5, lane = t & 31;
    int r = lane >> 2, c4 = lane & 3;
    int qt = gridDim.x - 1 - blockIdx.x;  // longest first
    int bh = blockIdx.y;
    int bidx = bh >> 4, head = bh & (H_ - 1);
    int len = g_len[bidx];
    int gqw = qt * 64 + w * 16;

    // Q fragments register-resident (scale 0.125 = 2^-3, exact)
    const float* Qb = Q + ((size_t)bh * L_ + gqw) * HD_;
    uint32_t qa[8][4];
    #pragma unroll
    for (int ks = 0; ks < 8; ks++) {
        qa[ks][0] = __float_as_uint(Qb[r * 64 + ks * 8 + c4] * 0.125f);
        qa[ks][1] = __float_as_uint(Qb[(r + 8) * 64 + ks * 8 + c4] * 0.125f);
        qa[ks][2] = __float_as_uint(Qb[r * 64 + ks * 8 + c4 + 4] * 0.125f);
        qa[ks][3] = __float_as_uint(Qb[(r + 8) * 64 + ks * 8 + c4 + 4] * 0.125f);
    }

    float o_[8][4] = {};
    float m0v = -1e30f, m1v = -1e30f, l0 = 0.f, l1 = 0.f;
    float* pw = Ps + w * 16 * PSTR;
    int nkt = qt + 1;

    auto load_stage = [&](int st, int kt2) {
        const float* Kb = K + ((size_t)bh * L_ + kt2 * 64) * HD_;
        const float* Vb = V + ((size_t)bh * L_ + kt2 * 64) * HD_;
        uint32_t sk = (uint32_t)__cvta_generic_to_shared(Ks + st * 64 * KSTR);
        uint32_t sv = (uint32_t)__cvta_generic_to_shared(Vs + st * 64 * VSTR);
        #pragma unroll
        for (int i = 0; i < 8; i++) {
            int cid = t + i * 128;
            int row = cid >> 4, kc = (cid & 15) * 4;
            CPA16(sk + (row * KSTR + kc) * 4, Kb + row * 64 + kc);
        }
        #pragma unroll
        for (int i = 0; i < 8; i++) {
            int cid = t + i * 128;
            int row = cid >> 4, kc = (cid & 15) * 4;
            CPA16(sv + (row * VSTR + kc) * 4, Vb + row * 64 + kc);
        }
    };

    load_stage(0, 0);
    CPA_COMMIT;
    #pragma unroll 1
    for (int kt = 0; kt < nkt; kt++) {
        if (kt + 1 < nkt) {
            load_stage((kt + 1) & 1, kt + 1);
            CPA_COMMIT;
            asm volatile("cp.async.wait_group 1;\n");
        } else {
            asm volatile("cp.async.wait_group 0;\n");
        }
        __syncthreads();
        int kbase = kt * 64;
        if (kbase <= gqw + 15 && kbase < len) {
            const float* ks_ = Ks + (kt & 1) * 64 * KSTR;
            const float* vs_ = Vs + (kt & 1) * 64 * VSTR;
            // S = Q K^T  (16 x 64 per warp)
            float s[8][4] = {};
            #pragma unroll
            for (int ks = 0; ks < 8; ks++) {
                uint32_t bf[8][2];
                #pragma unroll
                for (int nt = 0; nt < 8; nt++) {
                    const float* p = ks_ + (nt * 8 + r) * KSTR + ks * 8 + c4;
                    bf[nt][0] = __float_as_uint(p[0]);
                    bf[nt][1] = __float_as_uint(p[4]);
                }
                #pragma unroll
                for (int nt = 0; nt < 8; nt++)
                    mma_tf32(s[nt][0], s[nt][1], s[nt][2], s[nt][3],
                             qa[ks][0], qa[ks][1], qa[ks][2], qa[ks][3],
                             bf[nt][0], bf[nt][1]);
            }
            // masking (length + causal)
            int gq0 = gqw + r, gq1 = gq0 + 8;
            bool full = (kbase + 63 <= gqw) && (kbase + 64 <= len);
            if (!full) {
                #pragma unroll
                for (int nt = 0; nt < 8; nt++) {
                    int kc = kbase + nt * 8 + 2 * c4;
                    if (!(kc     <= gq0 && kc     < len)) s[nt][0] = -1e30f;
                    if (!(kc + 1 <= gq0 && kc + 1 < len)) s[nt][1] = -1e30f;
                    if (!(kc     <= gq1 && kc     < len)) s[nt][2] = -1e30f;
                    if (!(kc + 1 <= gq1 && kc + 1 < len)) s[nt][3] = -1e30f;
                }
            }
            // online softmax
            float mx0 = -1e30f, mx1 = -1e30f;
            #pragma unroll
            for (int nt = 0; nt < 8; nt++) {
                mx0 = fmaxf(mx0, fmaxf(s[nt][0], s[nt][1]));
                mx1 = fmaxf(mx1, fmaxf(s[nt][2], s[nt][3]));
            }
            mx0 = fmaxf(mx0, __shfl_xor_sync(0xffffffffu, mx0, 1));
            mx0 = fmaxf(mx0, __shfl_xor_sync(0xffffffffu, mx0, 2));
            mx1 = fmaxf(mx1, __shfl_xor_sync(0xffffffffu, mx1, 1));
            mx1 = fmaxf(mx1, __shfl_xor_sync(0xffffffffu, mx1, 2));
            float nm0 = fmaxf(m0v, mx0), nm1 = fmaxf(m1v, mx1);
            float sc0 = __expf(m0v - nm0), sc1 = __expf(m1v - nm1);
            m0v = nm0; m1v = nm1;
            float rs0 = 0.f, rs1 = 0.f;
            #pragma unroll
            for (int nt = 0; nt < 8; nt++) {
                s[nt][0] = __expf(s[nt][0] - nm0); rs0 += s[nt][0];
                s[nt][1] = __expf(s[nt][1] - nm0); rs0 += s[nt][1];
                s[nt][2] = __expf(s[nt][2] - nm1); rs1 += s[nt][2];
                s[nt][3] = __expf(s[nt][3] - nm1); rs1 += s[nt][3];
            }
            rs0 += __shfl_xor_sync(0xffffffffu, rs0, 1);
            rs0 += __shfl_xor_sync(0xffffffffu, rs0, 2);
            rs1 += __shfl_xor_sync(0xffffffffu, rs1, 1);
            rs1 += __shfl_xor_sync(0xffffffffu, rs1, 2);
            l0 = l0 * sc0 + rs0;
            l1 = l1 * sc1 + rs1;
            #pragma unroll
            for (int nt = 0; nt < 8; nt++) {
                o_[nt][0] *= sc0; o_[nt][1] *= sc0;
                o_[nt][2] *= sc1; o_[nt][3] *= sc1;
                float2 p0 = {tf32r(s[nt][0]), tf32r(s[nt][1])};
                float2 p1 = {tf32r(s[nt][2]), tf32r(s[nt][3])};
                *(float2*)(pw + r * PSTR + nt * 8 + 2 * c4) = p0;
                *(float2*)(pw + (r + 8) * PSTR + nt * 8 + 2 * c4) = p1;
            }
            __syncwarp();
            // O += P V
            #pragma unroll
            for (int ks = 0; ks < 8; ks++) {
                uint32_t a0 = __float_as_uint(pw[r * PSTR + ks * 8 + c4]);
                uint32_t a1 = __float_as_uint(pw[(r + 8) * PSTR + ks * 8 + c4]);
                uint32_t a2 = __float_as_uint(pw[r * PSTR + ks * 8 + c4 + 4]);
                uint32_t a3 = __float_as_uint(pw[(r + 8) * PSTR + ks * 8 + c4 + 4]);
                #pragma unroll
                for (int nt = 0; nt < 8; nt++) {
                    uint32_t b0 = __float_as_uint(vs_[(ks * 8 + c4) * VSTR + nt * 8 + r]);
                    uint32_t b1 = __float_as_uint(vs_[(ks * 8 + c4 + 4) * VSTR + nt * 8 + r]);
                    mma_tf32(o_[nt][0], o_[nt][1], o_[nt][2], o_[nt][3],
                             a0, a1, a2, a3, b0, b1);
                }
            }
            __syncwarp();
        }
        __syncthreads();
    }

    float inv0 = 1.0f / l0, inv1 = 1.0f / l1;
    size_t ob = (size_t)bidx * L_ + gqw;
    #pragma unroll
    for (int nt = 0; nt < 8; nt++) {
        int col = head * HD_ + nt * 8 + 2 * c4;
        float2 v0 = {tf32r(o_[nt][0] * inv0), tf32r(o_[nt][1] * inv0)};
        float2 v1 = {tf32r(o_[nt][2] * inv1), tf32r(o_[nt][3] * inv1)};
        *(float2*)(O + (ob + r) * D_ + col) = v0;
        *(float2*)(O + (ob + r + 8) * D_ + col) = v1;
    }
}

// ---------------- launch ----------------
extern "C" void kernel_launch(void* const* d_in, const int* in_sizes, int n_in,
                              void* d_out, int out_size) {
    const float* x     = (const float*)d_in[0];
    const void*  pmask = d_in[1];
    const float* Wq = (const float*)d_in[3];
    const float* bq = (const float*)d_in[4];
    const float* Wk = (const float*)d_in[5];
    const float* bk = (const float*)d_in[6];
    const float* Wv = (const float*)d_in[7];
    const float* bv = (const float*)d_in[8];
    const float* Wo = (const float*)d_in[9];
    const float* bo = (const float*)d_in[10];
    const float* g_pre = (const float*)d_in[11];
    const float* b_pre = (const float*)d_in[12];
    const float* g_ln  = (const float*)d_in[13];
    const float* b_ln  = (const float*)d_in[14];
    float* out = (float*)d_out;

    float *h, *q, *k, *v, *att, *y, *wqkv, *wo4;
    cudaGetSymbolAddress((void**)&h,    g_h);
    cudaGetSymbolAddress((void**)&q,    g_q);
    cudaGetSymbolAddress((void**)&k,    g_k);
    cudaGetSymbolAddress((void**)&v,    g_v);
    cudaGetSymbolAddress((void**)&att,  g_att);
    cudaGetSymbolAddress((void**)&y,    g_y);
    cudaGetSymbolAddress((void**)&wqkv, g_wqkv);
    cudaGetSymbolAddress((void**)&wo4,  g_wo4);

    const int gemm_smem = 3 * (128 + 128) * AST * (int)sizeof(float);  // 110592
    const int attn_smem = (2 * 64 * KSTR + 2 * 64 * VSTR + 4 * 16 * PSTR) * (int)sizeof(float); // 89088
    cudaFuncSetAttribute(tgemm_kernel,   cudaFuncAttributeMaxDynamicSharedMemorySize, gemm_smem);
    cudaFuncSetAttribute(attn_tc_kernel, cudaFuncAttributeMaxDynamicSharedMemorySize, attn_smem);

    mask_len_kernel<<<1, 256>>>((const unsigned int*)pmask);
    wround_kernel<<<(D_ * D_) / 256, 256>>>(Wq, Wk, Wv, Wo);
    ln_kernel<<<M_, 256>>>(x, g_pre, b_pre, h, 1);

    // fused QKV projection: N = 3072
    tgemm_kernel<<<dim3(3 * D_ / 128, M_ / 128), 256, gemm_smem>>>(
        h, wqkv, bq, bk, bv, nullptr, q, k, v, 1);

    attn_tc_kernel<<<dim3(L_ / 64, B_ * H_), 128, attn_smem>>>(q, k, v, att);

    // output projection + residual
    tgemm_kernel<<<dim3(D_ / 128, M_ / 128), 256, gemm_smem>>>(
        att, wo4, bo, bo, bo, h, y, y, y, 0);

    ln_kernel<<<M_, 256>>>(y, g_ln, b_ln, out, 0);
}

// round 9
// speedup vs baseline: 1.1183x; 1.0882x over previous
#include <cuda_runtime.h>
#include <cstdint>

#define B_ 4
#define L_ 2048
#define D_ 1024
#define H_ 16
#define HD_ 64
#define M_ 8192

// ---------------- scratch ----------------
__device__ float g_h[M_ * D_];
__device__ float g_q[M_ * D_];
__device__ float g_k[M_ * D_];
__device__ float g_v[M_ * D_];
__device__ float g_att[M_ * D_];
__device__ float g_y[M_ * D_];
__device__ float g_wqkv[3 * D_ * D_];
__device__ float g_wo4[D_ * D_];
__device__ int   g_len[B_];

// ---------------- helpers ----------------
__device__ __forceinline__ float tf32r(float x) {
    float y; asm("cvt.rna.tf32.f32 %0, %1;" : "=f"(y) : "f"(x)); return y;
}
__device__ __forceinline__ uint32_t fu(float x) { return __float_as_uint(x); }
#define CPA16(dst, src) asm volatile("cp.async.cg.shared.global [%0], [%1], 16;\n" ::"r"(dst), "l"(src))
#define CPA_COMMIT asm volatile("cp.async.commit_group;\n")

__device__ __forceinline__ void mma_tf32(float& c0, float& c1, float& c2, float& c3,
                                         uint32_t a0, uint32_t a1, uint32_t a2, uint32_t a3,
                                         uint32_t b0, uint32_t b1) {
    asm volatile(
        "mma.sync.aligned.m16n8k8.row.col.f32.tf32.tf32.f32 "
        "{%0,%1,%2,%3}, {%4,%5,%6,%7}, {%8,%9}, {%0,%1,%2,%3};\n"
        : "+f"(c0), "+f"(c1), "+f"(c2), "+f"(c3)
        : "r"(a0), "r"(a1), "r"(a2), "r"(a3), "r"(b0), "r"(b1));
}

// ---------------- mask -> lengths ----------------
__global__ void mask_len_kernel(const unsigned int* __restrict__ pw) {
    __shared__ int s_bad;
    int t = threadIdx.x;
    if (t == 0) s_bad = 0;
    if (t < B_) g_len[t] = L_;
    __syncthreads();
    int bad = 0;
    for (int i = t; i < (B_ * L_) / 4; i += 256) {
        unsigned v = pw[i];
        if (v != 0u && v != 1u && v != 0x3F800000u) bad = 1;
    }
    if (bad) atomicExch(&s_bad, 1);
    __syncthreads();
    if (s_bad) {
        const unsigned char* pb = (const unsigned char*)pw;
        for (int i = t; i < B_ * L_; i += 256)
            if (pb[i]) atomicMin(&g_len[i >> 11], i & (L_ - 1));
    } else {
        for (int i = t; i < B_ * L_; i += 256)
            if (pw[i]) atomicMin(&g_len[i >> 11], i & (L_ - 1));
    }
}

// ---------------- weight tf32 pre-round ----------------
__global__ void wround_kernel(const float* __restrict__ a, const float* __restrict__ b,
                              const float* __restrict__ c, const float* __restrict__ d) {
    int i = blockIdx.x * 256 + threadIdx.x;
    g_wqkv[i]               = tf32r(a[i]);
    g_wqkv[D_ * D_ + i]     = tf32r(b[i]);
    g_wqkv[2 * D_ * D_ + i] = tf32r(c[i]);
    g_wo4[i]                = tf32r(d[i]);
}

// ---------------- LayerNorm ----------------
__global__ void ln_kernel(const float* __restrict__ x, const float* __restrict__ gamma,
                          const float* __restrict__ beta, float* __restrict__ out, int rnd) {
    __shared__ float red[8];
    __shared__ float s_mu, s_rs;
    int row = blockIdx.x;
    int t = threadIdx.x;
    float4 v = ((const float4*)(x + (size_t)row * D_))[t];
    float s = v.x + v.y + v.z + v.w;
    #pragma unroll
    for (int o = 16; o; o >>= 1) s += __shfl_xor_sync(0xffffffffu, s, o);
    if ((t & 31) == 0) red[t >> 5] = s;
    __syncthreads();
    if (t == 0) {
        float tot = 0.f;
        #pragma unroll
        for (int i = 0; i < 8; i++) tot += red[i];
        s_mu = tot * (1.0f / D_);
    }
    __syncthreads();
    float mu = s_mu;
    float dx = v.x - mu, dy = v.y - mu, dz = v.z - mu, dw = v.w - mu;
    float ss = dx * dx + dy * dy + dz * dz + dw * dw;
    #pragma unroll
    for (int o = 16; o; o >>= 1) ss += __shfl_xor_sync(0xffffffffu, ss, o);
    __syncthreads();
    if ((t & 31) == 0) red[t >> 5] = ss;
    __syncthreads();
    if (t == 0) {
        float tot = 0.f;
        #pragma unroll
        for (int i = 0; i < 8; i++) tot += red[i];
        s_rs = rsqrtf(tot * (1.0f / D_) + 1e-5f);
    }
    __syncthreads();
    float rs = s_rs;
    float4 gv = ((const float4*)gamma)[t];
    float4 bv = ((const float4*)beta)[t];
    float4 o4;
    o4.x = dx * rs * gv.x + bv.x;
    o4.y = dy * rs * gv.y + bv.y;
    o4.z = dz * rs * gv.z + bv.z;
    o4.w = dw * rs * gv.w + bv.w;
    if (rnd) { o4.x = tf32r(o4.x); o4.y = tf32r(o4.y); o4.z = tf32r(o4.z); o4.w = tf32r(o4.w); }
    ((float4*)(out + (size_t)row * D_))[t] = o4;
}

// ---------------- tf32 TC GEMM: C = A(MxK) x W(NxK)^T + bias ----------------
// Block 128x128, 8 warps of 64x32, BK=32, 3-stage cp.async, chunk-swizzled
// smem (16B granularity, cc ^= (row&1)*4), vectorized LDS.128 fragments via
// k-slot permutation (phys k {4c4..4c4+3} -> slots of mma pair). 2 CTAs/SM.
#define BK_ 32
#define NK_ (D_ / BK_)
__global__ __launch_bounds__(256, 2) void tgemm_kernel(
    const float* __restrict__ A, const float* __restrict__ W,
    const float* __restrict__ bias0, const float* __restrict__ bias1,
    const float* __restrict__ bias2, const float* __restrict__ res,
    float* __restrict__ C0, float* __restrict__ C1, float* __restrict__ C2,
    int mode) {
    extern __shared__ float4 Sm4[];     // [3][1024] A chunks | [3][1024] B chunks
    int t = threadIdx.x, w = t >> 5, lane = t & 31;
    int r = lane >> 2, c4 = lane & 3;
    int par4 = (r & 1) * 4;
    int m0 = blockIdx.y * 128, n0 = blockIdx.x * 128;
    int wm = w >> 2, wn = w & 3;

    float acc[4][4][4] = {};

    auto load_stage = [&](int st, int k0) {
        float4* sa = Sm4 + st * 1024;
        float4* sb = Sm4 + 3072 + st * 1024;
        #pragma unroll
        for (int i = 0; i < 8; i++) {
            int cid = t + i * 256;
            if (cid < 1024) {
                int row = cid >> 3, cc = cid & 7;
                uint32_t dst = (uint32_t)__cvta_generic_to_shared(
                    sa + row * 8 + (cc ^ ((row & 1) * 4)));
                CPA16(dst, A + (size_t)(m0 + row) * D_ + k0 + cc * 4);
            } else {
                int c2 = cid - 1024;
                int row = c2 >> 3, cc = c2 & 7;
                uint32_t dst = (uint32_t)__cvta_generic_to_shared(
                    sb + row * 8 + (cc ^ ((row & 1) * 4)));
                CPA16(dst, W + (size_t)(n0 + row) * D_ + k0 + cc * 4);
            }
        }
    };

    load_stage(0, 0);
    CPA_COMMIT;
    load_stage(1, BK_);
    CPA_COMMIT;

    #pragma unroll 1
    for (int kb = 0; kb < NK_; kb++) {
        if (kb + 1 < NK_) asm volatile("cp.async.wait_group 1;\n");
        else              asm volatile("cp.async.wait_group 0;\n");
        __syncthreads();
        if (kb + 2 < NK_) {
            load_stage((kb + 2) % 3, (kb + 2) * BK_);
            CPA_COMMIT;
        }
        const float4* sa4 = Sm4 + (kb % 3) * 1024;
        const float4* sb4 = Sm4 + 3072 + (kb % 3) * 1024;
        #pragma unroll
        for (int p = 0; p < 2; p++) {
            int ccA = (4 * p + c4) ^ par4;
            float4 bf[4];
            #pragma unroll
            for (int nt = 0; nt < 4; nt++)
                bf[nt] = sb4[(wn * 32 + nt * 8 + r) * 8 + ccA];
            #pragma unroll
            for (int mt = 0; mt < 4; mt++) {
                float4 lo = sa4[(wm * 64 + mt * 16 + r) * 8 + ccA];
                float4 hi = sa4[(wm * 64 + mt * 16 + r + 8) * 8 + ccA];
                #pragma unroll
                for (int nt = 0; nt < 4; nt++) {
                    mma_tf32(acc[mt][nt][0], acc[mt][nt][1], acc[mt][nt][2], acc[mt][nt][3],
                             fu(lo.x), fu(hi.x), fu(lo.y), fu(hi.y),
                             fu(bf[nt].x), fu(bf[nt].y));
                    mma_tf32(acc[mt][nt][0], acc[mt][nt][1], acc[mt][nt][2], acc[mt][nt][3],
                             fu(lo.z), fu(hi.z), fu(lo.w), fu(hi.w),
                             fu(bf[nt].z), fu(bf[nt].w));
                }
            }
        }
        __syncthreads();
    }

    int mrow = m0 + wm * 64, ncol = n0 + wn * 32;
    if (mode == 1) {
        int mat = ncol >> 10;
        int dbase = ncol & 1023;
        const float* bias = (mat == 0) ? bias0 : (mat == 1) ? bias1 : bias2;
        float* C = (mat == 0) ? C0 : (mat == 1) ? C1 : C2;
        #pragma unroll
        for (int mt = 0; mt < 4; mt++) {
            int row0 = mrow + mt * 16 + r;
            int bidx = row0 >> 11, l = row0 & (L_ - 1);
            #pragma unroll
            for (int nt = 0; nt < 4; nt++) {
                int dcol = dbase + nt * 8 + 2 * c4;
                int head = dcol >> 6, hd = dcol & 63;
                float b0 = bias[dcol], b1 = bias[dcol + 1];
                float* d0 = C + ((size_t)(bidx * H_ + head) * L_ + l) * HD_ + hd;
                float* d1 = C + ((size_t)(bidx * H_ + head) * L_ + l + 8) * HD_ + hd;
                float2 v0 = {tf32r(acc[mt][nt][0] + b0), tf32r(acc[mt][nt][1] + b1)};
                float2 v1 = {tf32r(acc[mt][nt][2] + b0), tf32r(acc[mt][nt][3] + b1)};
                *(float2*)d0 = v0;
                *(float2*)d1 = v1;
            }
        }
    } else {
        #pragma unroll
        for (int mt = 0; mt < 4; mt++) {
            int row0 = mrow + mt * 16 + r;
            #pragma unroll
            for (int nt = 0; nt < 4; nt++) {
                int col = ncol + nt * 8 + 2 * c4;
                float b0 = bias0[col], b1 = bias0[col + 1];
                float2 r0 = *(const float2*)(res + (size_t)row0 * D_ + col);
                float2 r1 = *(const float2*)(res + (size_t)(row0 + 8) * D_ + col);
                float2 v0 = {acc[mt][nt][0] + b0 + r0.x, acc[mt][nt][1] + b1 + r0.y};
                float2 v1 = {acc[mt][nt][2] + b0 + r1.x, acc[mt][nt][3] + b1 + r1.y};
                *(float2*)(C0 + (size_t)row0 * D_ + col) = v0;
                *(float2*)(C0 + (size_t)(row0 + 8) * D_ + col) = v1;
            }
        }
    }
}

// ---------------- tf32 TC flash attention ----------------
// CTA: 64 query rows, 4 warps x 16 rows, K-tile 64, double-buffered.
// K staged chunk-swizzled; S-gemm B-frags via LDS.128 (same slot permutation,
// Q global loads re-indexed to match). P/V paths scalar as before. 2 CTAs/SM.
#define VSTR 72
#define PSTR 68
__global__ __launch_bounds__(128, 2) void attn_tc_kernel(
    const float* __restrict__ Q, const float* __restrict__ K,
    const float* __restrict__ V, float* __restrict__ O) {
    extern __shared__ float sm[];
    float4* Ks4 = (float4*)sm;            // [2][64*16] chunk-swizzled
    float* Vs = sm + 2 * 1024 * 4;        // [2][64][72]
    float* Ps = Vs + 2 * 64 * VSTR;       // [4][16][68]
    int t = threadIdx.x, w = t >> 5, lane = t & 31;
    int r = lane >> 2, c4 = lane & 3;
    int par4 = (r & 1) * 4;
    int qt = gridDim.x - 1 - blockIdx.x;
    int bh = blockIdx.y;
    int bidx = bh >> 4, head = bh & (H_ - 1);
    int len = g_len[bidx];
    int gqw = qt * 64 + w * 16;

    // Q fragments, slot convention: mma (p,s): slot c4 <- phys dim 16p+4c4+2s
    const float* Qb = Q + ((size_t)bh * L_ + gqw) * HD_;
    uint32_t qa[8][4];
    #pragma unroll
    for (int p = 0; p < 4; p++)
        #pragma unroll
        for (int s2 = 0; s2 < 2; s2++) {
            int d0 = 16 * p + 4 * c4 + 2 * s2;
            float2 lo = *(const float2*)(Qb + r * 64 + d0);
            float2 hi = *(const float2*)(Qb + (r + 8) * 64 + d0);
            qa[2 * p + s2][0] = fu(lo.x * 0.125f);
            qa[2 * p + s2][1] = fu(hi.x * 0.125f);
            qa[2 * p + s2][2] = fu(lo.y * 0.125f);
            qa[2 * p + s2][3] = fu(hi.y * 0.125f);
        }

    float o_[8][4] = {};
    float m0v = -1e30f, m1v = -1e30f, l0 = 0.f, l1 = 0.f;
    float* pw = Ps + w * 16 * PSTR;
    int nkt = qt + 1;

    auto load_stage = [&](int st, int kt2) {
        const float* Kb = K + ((size_t)bh * L_ + kt2 * 64) * HD_;
        const float* Vb = V + ((size_t)bh * L_ + kt2 * 64) * HD_;
        float4* sk = Ks4 + st * 1024;
        uint32_t sv = (uint32_t)__cvta_generic_to_shared(Vs + st * 64 * VSTR);
        #pragma unroll
        for (int i = 0; i < 8; i++) {
            int cid = t + i * 128;
            int row = cid >> 4, cc = cid & 15;
            uint32_t dst = (uint32_t)__cvta_generic_to_shared(
                sk + row * 16 + (cc ^ ((row & 1) * 4)));
            CPA16(dst, Kb + row * 64 + cc * 4);
        }
        #pragma unroll
        for (int i = 0; i < 8; i++) {
            int cid = t + i * 128;
            int row = cid >> 4, kc = (cid & 15) * 4;
            CPA16(sv + (row * VSTR + kc) * 4, Vb + row * 64 + kc);
        }
    };

    load_stage(0, 0);
    CPA_COMMIT;
    #pragma unroll 1
    for (int kt = 0; kt < nkt; kt++) {
        if (kt + 1 < nkt) {
            load_stage((kt + 1) & 1, kt + 1);
            CPA_COMMIT;
            asm volatile("cp.async.wait_group 1;\n");
        } else {
            asm volatile("cp.async.wait_group 0;\n");
        }
        __syncthreads();
        int kbase = kt * 64;
        if (kbase <= gqw + 15 && kbase < len) {
            const float4* ks4 = Ks4 + (kt & 1) * 1024;
            const float* vs_ = Vs + (kt & 1) * 64 * VSTR;
            // ---- S = Q K^T (vectorized K fragments) ----
            float s[8][4] = {};
            #pragma unroll
            for (int p = 0; p < 4; p++) {
                int ccK = (4 * p + c4) ^ par4;
                #pragma unroll
                for (int nt = 0; nt < 8; nt++) {
                    float4 kb = ks4[(nt * 8 + r) * 16 + ccK];
                    mma_tf32(s[nt][0], s[nt][1], s[nt][2], s[nt][3],
                             qa[2 * p][0], qa[2 * p][1], qa[2 * p][2], qa[2 * p][3],
                             fu(kb.x), fu(kb.y));
                    mma_tf32(s[nt][0], s[nt][1], s[nt][2], s[nt][3],
                             qa[2 * p + 1][0], qa[2 * p + 1][1], qa[2 * p + 1][2], qa[2 * p + 1][3],
                             fu(kb.z), fu(kb.w));
                }
            }
            // masking (length + causal); key mapping unchanged (n-dim not permuted)
            int gq0 = gqw + r, gq1 = gq0 + 8;
            bool full = (kbase + 63 <= gqw) && (kbase + 64 <= len);
            if (!full) {
                #pragma unroll
                for (int nt = 0; nt < 8; nt++) {
                    int kc = kbase + nt * 8 + 2 * c4;
                    if (!(kc     <= gq0 && kc     < len)) s[nt][0] = -1e30f;
                    if (!(kc + 1 <= gq0 && kc + 1 < len)) s[nt][1] = -1e30f;
                    if (!(kc     <= gq1 && kc     < len)) s[nt][2] = -1e30f;
                    if (!(kc + 1 <= gq1 && kc + 1 < len)) s[nt][3] = -1e30f;
                }
            }
            // online softmax
            float mx0 = -1e30f, mx1 = -1e30f;
            #pragma unroll
            for (int nt = 0; nt < 8; nt++) {
                mx0 = fmaxf(mx0, fmaxf(s[nt][0], s[nt][1]));
                mx1 = fmaxf(mx1, fmaxf(s[nt][2], s[nt][3]));
            }
            mx0 = fmaxf(mx0, __shfl_xor_sync(0xffffffffu, mx0, 1));
            mx0 = fmaxf(mx0, __shfl_xor_sync(0xffffffffu, mx0, 2));
            mx1 = fmaxf(mx1, __shfl_xor_sync(0xffffffffu, mx1, 1));
            mx1 = fmaxf(mx1, __shfl_xor_sync(0xffffffffu, mx1, 2));
            float nm0 = fmaxf(m0v, mx0), nm1 = fmaxf(m1v, mx1);
            float sc0 = __expf(m0v - nm0), sc1 = __expf(m1v - nm1);
            m0v = nm0; m1v = nm1;
            float rs0 = 0.f, rs1 = 0.f;
            #pragma unroll
            for (int nt = 0; nt < 8; nt++) {
                s[nt][0] = __expf(s[nt][0] - nm0); rs0 += s[nt][0];
                s[nt][1] = __expf(s[nt][1] - nm0); rs0 += s[nt][1];
                s[nt][2] = __expf(s[nt][2] - nm1); rs1 += s[nt][2];
                s[nt][3] = __expf(s[nt][3] - nm1); rs1 += s[nt][3];
            }
            rs0 += __shfl_xor_sync(0xffffffffu, rs0, 1);
            rs0 += __shfl_xor_sync(0xffffffffu, rs0, 2);
            rs1 += __shfl_xor_sync(0xffffffffu, rs1, 1);
            rs1 += __shfl_xor_sync(0xffffffffu, rs1, 2);
            l0 = l0 * sc0 + rs0;
            l1 = l1 * sc1 + rs1;
            #pragma unroll
            for (int nt = 0; nt < 8; nt++) {
                o_[nt][0] *= sc0; o_[nt][1] *= sc0;
                o_[nt][2] *= sc1; o_[nt][3] *= sc1;
                float2 p0 = {tf32r(s[nt][0]), tf32r(s[nt][1])};
                float2 p1 = {tf32r(s[nt][2]), tf32r(s[nt][3])};
                *(float2*)(pw + r * PSTR + nt * 8 + 2 * c4) = p0;
                *(float2*)(pw + (r + 8) * PSTR + nt * 8 + 2 * c4) = p1;
            }
            __syncwarp();
            // ---- O += P V (standard slot convention, scalar frags) ----
            #pragma unroll
            for (int ks = 0; ks < 8; ks++) {
                uint32_t a0 = fu(pw[r * PSTR + ks * 8 + c4]);
                uint32_t a1 = fu(pw[(r + 8) * PSTR + ks * 8 + c4]);
                uint32_t a2 = fu(pw[r * PSTR + ks * 8 + c4 + 4]);
                uint32_t a3 = fu(pw[(r + 8) * PSTR + ks * 8 + c4 + 4]);
                #pragma unroll
                for (int nt = 0; nt < 8; nt++) {
                    uint32_t b0 = fu(vs_[(ks * 8 + c4) * VSTR + nt * 8 + r]);
                    uint32_t b1 = fu(vs_[(ks * 8 + c4 + 4) * VSTR + nt * 8 + r]);
                    mma_tf32(o_[nt][0], o_[nt][1], o_[nt][2], o_[nt][3],
                             a0, a1, a2, a3, b0, b1);
                }
            }
            __syncwarp();
        }
        __syncthreads();
    }

    float inv0 = 1.0f / l0, inv1 = 1.0f / l1;
    size_t ob = (size_t)bidx * L_ + gqw;
    #pragma unroll
    for (int nt = 0; nt < 8; nt++) {
        int col = head * HD_ + nt * 8 + 2 * c4;
        float2 v0 = {tf32r(o_[nt][0] * inv0), tf32r(o_[nt][1] * inv0)};
        float2 v1 = {tf32r(o_[nt][2] * inv1), tf32r(o_[nt][3] * inv1)};
        *(float2*)(O + (ob + r) * D_ + col) = v0;
        *(float2*)(O + (ob + r + 8) * D_ + col) = v1;
    }
}

// ---------------- launch ----------------
extern "C" void kernel_launch(void* const* d_in, const int* in_sizes, int n_in,
                              void* d_out, int out_size) {
    const float* x     = (const float*)d_in[0];
    const void*  pmask = d_in[1];
    const float* Wq = (const float*)d_in[3];
    const float* bq = (const float*)d_in[4];
    const float* Wk = (const float*)d_in[5];
    const float* bk = (const float*)d_in[6];
    const float* Wv = (const float*)d_in[7];
    const float* bv = (const float*)d_in[8];
    const float* Wo = (const float*)d_in[9];
    const float* bo = (const float*)d_in[10];
    const float* g_pre = (const float*)d_in[11];
    const float* b_pre = (const float*)d_in[12];
    const float* g_ln  = (const float*)d_in[13];
    const float* b_ln  = (const float*)d_in[14];
    float* out = (float*)d_out;

    float *h, *q, *k, *v, *att, *y, *wqkv, *wo4;
    cudaGetSymbolAddress((void**)&h,    g_h);
    cudaGetSymbolAddress((void**)&q,    g_q);
    cudaGetSymbolAddress((void**)&k,    g_k);
    cudaGetSymbolAddress((void**)&v,    g_v);
    cudaGetSymbolAddress((void**)&att,  g_att);
    cudaGetSymbolAddress((void**)&y,    g_y);
    cudaGetSymbolAddress((void**)&wqkv, g_wqkv);
    cudaGetSymbolAddress((void**)&wo4,  g_wo4);

    const int gemm_smem = 6 * 1024 * 16;  // 98304: 3 stages x (A 16KB + B 16KB)
    const int attn_smem = 2 * 1024 * 16 + (2 * 64 * VSTR + 4 * 16 * PSTR) * (int)sizeof(float); // 87040
    cudaFuncSetAttribute(tgemm_kernel,   cudaFuncAttributeMaxDynamicSharedMemorySize, gemm_smem);
    cudaFuncSetAttribute(attn_tc_kernel, cudaFuncAttributeMaxDynamicSharedMemorySize, attn_smem);

    mask_len_kernel<<<1, 256>>>((const unsigned int*)pmask);
    wround_kernel<<<(D_ * D_) / 256, 256>>>(Wq, Wk, Wv, Wo);
    ln_kernel<<<M_, 256>>>(x, g_pre, b_pre, h, 1);

    // fused QKV projection: N = 3072
    tgemm_kernel<<<dim3(3 * D_ / 128, M_ / 128), 256, gemm_smem>>>(
        h, wqkv, bq, bk, bv, nullptr, q, k, v, 1);

    attn_tc_kernel<<<dim3(L_ / 64, B_ * H_), 128, attn_smem>>>(q, k, v, att);

    // output projection + residual
    tgemm_kernel<<<dim3(D_ / 128, M_ / 128), 256, gemm_smem>>>(
        att, wo4, bo, bo, bo, h, y, y, y, 0);

    ln_kernel<<<M_, 256>>>(y, g_ln, b_ln, out, 0);
}